// round 6
// baseline (speedup 1.0000x reference)
#include <cuda_runtime.h>
#include <cuda_bf16.h>

constexpr int B = 2, T = 1024, D = 768, S = 128, HALF = 24;
constexpr int ROWS = B * D;  // 1536

// ---- device scratch (static: no allocation) ----
__device__ float g_Wt[D * S];      // W^T: Wt[c*S+s] = W[s][c]
__device__ float g_xq[B * T * D];  // x @ M_inputs, natural (b,t,c) layout

// ============================================================
// W[s,c] = sum_k (BC[s,k] + BC[s,k+24]) * M_filters[k,c], stored Wt[c*S+s]
// ============================================================
__global__ void prep_w(const float* __restrict__ BC, const float* __restrict__ Mfil) {
    int s = blockIdx.x;   // 0..127
    int c = threadIdx.x;  // 0..767
    float acc = 0.f;
#pragma unroll
    for (int k = 0; k < HALF; k++) {
        float bsum = BC[s * 2 * HALF + k] + BC[s * 2 * HALF + HALF + k];
        acc = fmaf(bsum, Mfil[k * D + c], acc);
    }
    g_Wt[(size_t)c * S + s] = acc;
}

// ============================================================
// Projection: g_xq[b,t,c] = sum_k x[b,t,k] * Min[k,c]
// Block = 16 t-rows staged in smem; thread tid computes c = tid, tid+256,
// tid+512 for all 16 t. Min reads coalesced; xs reads are broadcasts.
// ============================================================
__global__ void __launch_bounds__(256) proj_kernel(const float* __restrict__ x,
                                                   const float* __restrict__ Min) {
    __shared__ float xs[16 * 768];
    const int t0 = blockIdx.x * 16;
    const int b = blockIdx.y;
    const int tid = threadIdx.x;

    for (int idx = tid; idx < 16 * 768; idx += 256) {
        int tt = idx / 768, k = idx % 768;
        xs[idx] = x[((size_t)b * T + t0 + tt) * D + k];
    }
    __syncthreads();

    float acc[16][3];
#pragma unroll
    for (int tt = 0; tt < 16; tt++)
        acc[tt][0] = acc[tt][1] = acc[tt][2] = 0.f;

#pragma unroll 4
    for (int k = 0; k < D; k++) {
        float m0 = Min[(size_t)k * D + tid];
        float m1 = Min[(size_t)k * D + tid + 256];
        float m2 = Min[(size_t)k * D + tid + 512];
#pragma unroll
        for (int tt = 0; tt < 16; tt++) {
            float xv = xs[tt * 768 + k];
            acc[tt][0] = fmaf(xv, m0, acc[tt][0]);
            acc[tt][1] = fmaf(xv, m1, acc[tt][1]);
            acc[tt][2] = fmaf(xv, m2, acc[tt][2]);
        }
    }

#pragma unroll
    for (int tt = 0; tt < 16; tt++) {
        size_t base = ((size_t)b * T + t0 + tt) * D;
        g_xq[base + tid]       = acc[tt][0];
        g_xq[base + tid + 256] = acc[tt][1];
        g_xq[base + tid + 512] = acc[tt][2];
    }
}

// ============================================================
// Scan: one warp per row (b,c). Lane l owns states 4l..4l+3.
// h_t = A*h_{t-1} + x_t (broadcast); y_t = sum_s h_s W[s,c] via per-lane
// dot + warp shuffle reduce. Output written as f32, bf16-ROUNDED to match
// the reference's bf16 quantization grid.
// ============================================================
__global__ void __launch_bounds__(256) scan_kernel(const float* __restrict__ A,
                                                   float* __restrict__ out) {
    const int warp = threadIdx.x >> 5;
    const int lane = threadIdx.x & 31;
    const int row = blockIdx.x * 8 + warp;  // 0..1535
    const int b = row / D;
    const int c = row % D;

    const float4 A4 = *(const float4*)(A + 4 * lane);
    const float4 W4 = *(const float4*)(g_Wt + (size_t)c * S + 4 * lane);

    const float* xr = g_xq + (size_t)b * T * D + c;
    float* yo = out + (size_t)b * T * D + c;

    float4 h = make_float4(0.f, 0.f, 0.f, 0.f);

#pragma unroll 4
    for (int t = 0; t < T; t++) {
        float xv = xr[(size_t)t * D];  // same addr across lanes: broadcast
        h.x = fmaf(A4.x, h.x, xv);
        h.y = fmaf(A4.y, h.y, xv);
        h.z = fmaf(A4.z, h.z, xv);
        h.w = fmaf(A4.w, h.w, xv);
        float p = h.x * W4.x;
        p = fmaf(h.y, W4.y, p);
        p = fmaf(h.z, W4.z, p);
        p = fmaf(h.w, W4.w, p);
        p += __shfl_down_sync(0xffffffffu, p, 16);
        p += __shfl_down_sync(0xffffffffu, p, 8);
        p += __shfl_down_sync(0xffffffffu, p, 4);
        p += __shfl_down_sync(0xffffffffu, p, 2);
        p += __shfl_down_sync(0xffffffffu, p, 1);
        if (lane == 0)
            yo[(size_t)t * D] = __bfloat162float(__float2bfloat16(p));
    }
}

// ============================================================
extern "C" void kernel_launch(void* const* d_in, const int* in_sizes, int n_in,
                              void* d_out, int out_size) {
    const float* x = nullptr;
    const float *Min = nullptr, *Mfil = nullptr, *A = nullptr, *BC = nullptr;
    for (int i = 0; i < n_in; i++) {
        switch (in_sizes[i]) {  // all five element counts are distinct
            case B * T * D:     x    = (const float*)d_in[i]; break;  // 1572864
            case D * D:         Min  = (const float*)d_in[i]; break;  // 589824
            case HALF * D:      Mfil = (const float*)d_in[i]; break;  // 18432
            case S:             A    = (const float*)d_in[i]; break;  // 128
            case S * 2 * HALF:  BC   = (const float*)d_in[i]; break;  // 6144
        }
    }

    prep_w<<<S, D>>>(BC, Mfil);
    proj_kernel<<<dim3(T / 16, B), 256>>>(x, Min);
    scan_kernel<<<ROWS / 8, 256>>>(A, (float*)d_out);
}

// round 7
// speedup vs baseline: 4.1888x; 4.1888x over previous
#include <cuda_runtime.h>
#include <cuda_bf16.h>

typedef unsigned long long ull;

#define DI static __device__ __forceinline__

// ---- packed f32x2 helpers (sm_100a) ----
DI ull ffma2(ull a, ull b, ull c) {
    ull d;
    asm("fma.rn.f32x2 %0, %1, %2, %3;" : "=l"(d) : "l"(a), "l"(b), "l"(c));
    return d;
}
DI ull fmul2(ull a, ull b) {
    ull d;
    asm("mul.rn.f32x2 %0, %1, %2;" : "=l"(d) : "l"(a), "l"(b));
    return d;
}
DI ull pack2(float lo, float hi) {
    ull d;
    asm("mov.b64 %0, {%1, %2};" : "=l"(d) : "f"(lo), "f"(hi));
    return d;
}
DI float2 unpack2(ull v) {
    float2 r;
    asm("mov.b64 {%0, %1}, %2;" : "=f"(r.x), "=f"(r.y) : "l"(v));
    return r;
}

constexpr int B = 2, T = 1024, D = 768, S = 128, HALF = 24;
constexpr int ROWS = B * D;            // 1536
constexpr int KSPLIT = 3, KSEG = 256;  // 3 * 256 = 768 = K

// ---- device scratch (static: no allocation) ----
__device__ float g_Wt[D * S];               // W^T: Wt[c*S+s]
__device__ float g_xp[KSPLIT * ROWS * T];   // K-split partials of x@M, (row,t)
__device__ float g_yp[ROWS * T];            // scan output, (row,t)

// ============================================================
// W[s,c] = sum_k (BC[s,k] + BC[s,k+24]) * M_filters[k,c], stored Wt[c*S+s]
// ============================================================
__global__ void prep_w(const float* __restrict__ BC, const float* __restrict__ Mfil) {
    int s = blockIdx.x;   // 0..127
    int c = threadIdx.x;  // 0..767
    float acc = 0.f;
#pragma unroll
    for (int k = 0; k < HALF; k++) {
        float bsum = BC[s * 2 * HALF + k] + BC[s * 2 * HALF + HALF + k];
        acc = fmaf(bsum, Mfil[k * D + c], acc);
    }
    g_Wt[(size_t)c * S + s] = acc;
}

// ============================================================
// GEMM: xp[ks][b*768+c][t] = sum_{k in seg ks} M[k,c] * x[b,t,k]
// 128(c) x 128(t) tile, 256 threads, 8x8 microtile via f32x2 pairs on t.
// K split into 3 segments -> 288 CTAs (~2 full waves).
// ============================================================
__global__ void __launch_bounds__(256, 2) gemm_kernel(const float* __restrict__ x,
                                                      const float* __restrict__ Min) {
    const int cbase = blockIdx.x * 128;
    const int tbase = blockIdx.y * 128;
    const int b     = blockIdx.z / KSPLIT;
    const int ks    = blockIdx.z % KSPLIT;
    const int kbase = ks * KSEG;

    __shared__ float As[8][132];  // As[k][c]
    __shared__ float Bs[8][132];  // Bs[k][t]

    const int tid = threadIdx.x;
    const int a_k = tid >> 5;
    const int a_c = (tid & 31) << 2;
    const int b_t = tid >> 1;
    const int b_k = (tid & 1) << 2;
    const int tx = tid & 15;   // t microtile
    const int ty = tid >> 4;   // c microtile

    const float* Ap = Min + (size_t)(kbase + a_k) * D + cbase + a_c;
    const float* Bp = x + ((size_t)b * T + tbase + b_t) * D + kbase + b_k;

    ull acc[8][4];
#pragma unroll
    for (int i = 0; i < 8; i++)
#pragma unroll
        for (int j = 0; j < 4; j++) acc[i][j] = 0ull;

    float4 av = *(const float4*)Ap;
    float4 bv = *(const float4*)Bp;

    for (int kt = 0; kt < KSEG / 8; kt++) {
        __syncthreads();
        *(float4*)&As[a_k][a_c] = av;
        Bs[b_k + 0][b_t] = bv.x;
        Bs[b_k + 1][b_t] = bv.y;
        Bs[b_k + 2][b_t] = bv.z;
        Bs[b_k + 3][b_t] = bv.w;
        __syncthreads();
        if (kt + 1 < KSEG / 8) {  // register prefetch of next k-tile
            Ap += 8 * D;
            Bp += 8;
            av = *(const float4*)Ap;
            bv = *(const float4*)Bp;
        }
#pragma unroll
        for (int kk = 0; kk < 8; kk++) {
            float4 af0 = *(const float4*)&As[kk][ty * 8];
            float4 af1 = *(const float4*)&As[kk][ty * 8 + 4];
            ull b20 = *(const ull*)&Bs[kk][tx * 8];
            ull b21 = *(const ull*)&Bs[kk][tx * 8 + 2];
            ull b22 = *(const ull*)&Bs[kk][tx * 8 + 4];
            ull b23 = *(const ull*)&Bs[kk][tx * 8 + 6];
            float a[8] = {af0.x, af0.y, af0.z, af0.w, af1.x, af1.y, af1.z, af1.w};
#pragma unroll
            for (int i = 0; i < 8; i++) {
                ull ai = pack2(a[i], a[i]);
                acc[i][0] = ffma2(ai, b20, acc[i][0]);
                acc[i][1] = ffma2(ai, b21, acc[i][1]);
                acc[i][2] = ffma2(ai, b22, acc[i][2]);
                acc[i][3] = ffma2(ai, b23, acc[i][3]);
            }
        }
    }

    float* outbase = g_xp + (size_t)ks * ROWS * T;
#pragma unroll
    for (int i = 0; i < 8; i++) {
        int row = b * D + cbase + ty * 8 + i;
        float* dst = outbase + (size_t)row * T + tbase + tx * 8;
        float2 p0 = unpack2(acc[i][0]);
        float2 p1 = unpack2(acc[i][1]);
        float2 p2 = unpack2(acc[i][2]);
        float2 p3 = unpack2(acc[i][3]);
        *(float4*)dst       = make_float4(p0.x, p0.y, p1.x, p1.y);
        *(float4*)(dst + 4) = make_float4(p2.x, p2.y, p3.x, p3.y);
    }
}

// ============================================================
// Scan: one warp per row (b,c). Lane owns 4 states as two f32x2 pairs.
// Per-step lane partials staged in smem; cross-lane transpose-reduce every
// 32 steps (no shuffle chain). x prefetched one 32-block ahead, coalesced.
// ============================================================
constexpr int SCAN_WARPS = 4;

__global__ void __launch_bounds__(SCAN_WARPS * 32) scan_kernel(const float* __restrict__ Ain) {
    __shared__ float sx[SCAN_WARPS][32];
    __shared__ float sp[SCAN_WARPS][32 * 33];

    const int warp = threadIdx.x >> 5;
    const int lane = threadIdx.x & 31;
    const int row = blockIdx.x * SCAN_WARPS + warp;  // 0..1535
    const int c = row % D;

    // states for this lane: {2l, 2l+1} and {64+2l, 64+2l+1}
    ull A20 = *(const ull*)(Ain + 2 * lane);
    ull A21 = *(const ull*)(Ain + 64 + 2 * lane);
    const float* Wr = g_Wt + (size_t)c * S;
    ull W20 = *(const ull*)(Wr + 2 * lane);
    ull W21 = *(const ull*)(Wr + 64 + 2 * lane);

    const float* x0 = g_xp + (size_t)row * T;
    const float* x1 = x0 + (size_t)ROWS * T;
    const float* x2 = x1 + (size_t)ROWS * T;
    float* yr = g_yp + (size_t)row * T;

    float* sxm = sx[warp];
    float* spm = sp[warp];

    ull h0 = 0ull, h1 = 0ull;

    float xv = x0[lane] + x1[lane] + x2[lane];  // sum K-split partials
    for (int t0 = 0; t0 < T; t0 += 32) {
        sxm[lane] = xv;
        __syncwarp();
        if (t0 + 32 < T) {  // prefetch next block
            int t = t0 + 32 + lane;
            xv = x0[t] + x1[t] + x2[t];
        }
#pragma unroll
        for (int tt = 0; tt < 32; tt++) {
            float xs = sxm[tt];
            ull xx = pack2(xs, xs);
            h0 = ffma2(A20, h0, xx);
            h1 = ffma2(A21, h1, xx);
            ull p = fmul2(h0, W20);
            p = ffma2(h1, W21, p);
            float2 pf = unpack2(p);
            spm[tt * 33 + lane] = pf.x + pf.y;  // conflict-free
        }
        __syncwarp();
        // lane j reduces time index j over the 32 source lanes
        const float* col = spm + lane * 33;
        float a0 = 0.f, a1 = 0.f, a2 = 0.f, a3 = 0.f;
#pragma unroll
        for (int l = 0; l < 32; l += 4) {
            a0 += col[l];
            a1 += col[l + 1];
            a2 += col[l + 2];
            a3 += col[l + 3];
        }
        yr[t0 + lane] = (a0 + a1) + (a2 + a3);
        __syncwarp();
    }
}

// ============================================================
// Transpose (row,t) fp32 -> (b,t,c), output f32 on bf16 grid
// ============================================================
__global__ void transpose_kernel(float* __restrict__ out) {
    __shared__ float tile[32][33];
    const int t0 = blockIdx.x * 32;
    const int c0 = blockIdx.y * 32;
    const int b = blockIdx.z;
    const int tx = threadIdx.x, ty = threadIdx.y;
#pragma unroll
    for (int i = 0; i < 32; i += 8)
        tile[ty + i][tx] = g_yp[(size_t)(b * D + c0 + ty + i) * T + t0 + tx];
    __syncthreads();
#pragma unroll
    for (int i = 0; i < 32; i += 8) {
        float v = tile[tx][ty + i];
        out[(size_t)(b * T + t0 + ty + i) * D + c0 + tx] =
            __bfloat162float(__float2bfloat16(v));
    }
}

// ============================================================
extern "C" void kernel_launch(void* const* d_in, const int* in_sizes, int n_in,
                              void* d_out, int out_size) {
    const float* x = nullptr;
    const float *Min = nullptr, *Mfil = nullptr, *A = nullptr, *BC = nullptr;
    for (int i = 0; i < n_in; i++) {
        switch (in_sizes[i]) {  // all five element counts are distinct
            case B * T * D:     x    = (const float*)d_in[i]; break;  // 1572864
            case D * D:         Min  = (const float*)d_in[i]; break;  // 589824
            case HALF * D:      Mfil = (const float*)d_in[i]; break;  // 18432
            case S:             A    = (const float*)d_in[i]; break;  // 128
            case S * 2 * HALF:  BC   = (const float*)d_in[i]; break;  // 6144
        }
    }

    prep_w<<<S, D>>>(BC, Mfil);
    gemm_kernel<<<dim3(D / 128, T / 128, B * KSPLIT), 256>>>(x, Min);
    scan_kernel<<<ROWS / SCAN_WARPS, SCAN_WARPS * 32>>>(A);
    transpose_kernel<<<dim3(T / 32, D / 32, B), dim3(32, 8)>>>((float*)d_out);
}